// round 3
// baseline (speedup 1.0000x reference)
#include <cuda_runtime.h>
#include <cuda_bf16.h>
#include <math.h>

// ---------------- problem constants ----------------
#define B_   32
#define LSEQ 128
#define T_   127          // L-1
#define S_   256
#define H_   512
#define NH_  8
#define HD_  64
#define V_   8000
#define M_Q  (B_ * T_)    // 4064
#define M_KV (B_ * S_)    // 8192

// ---------------- scratch (device globals; no allocation allowed) ----------------
__device__ float g_emb [M_Q * H_];        // gathered embeddings
__device__ float g_xg  [M_Q * 4 * H_];    // input-gate preactivations (+biases)
__device__ float g_lstm[M_Q * H_];        // lstm hidden sequence
__device__ float g_hbuf[2 * B_ * H_];     // double-buffered h
__device__ float g_cbuf[B_ * H_];         // cell state
__device__ float g_q   [M_Q * H_];
__device__ float g_k   [M_KV * H_];
__device__ float g_v   [M_KV * H_];
__device__ float g_ctx [M_Q * H_];
__device__ float g_comb[M_Q * H_];

// software grid barrier state (returns to initial-compatible state every launch)
__device__ unsigned g_bar_count = 0;
__device__ volatile unsigned g_bar_gen = 0;

// ---------------- gather: emb[m] = embedding[targets[b][t]] ----------------
__global__ void gather_kernel(const int* __restrict__ targets,
                              const float* __restrict__ embedding,
                              float* __restrict__ emb)
{
    int idx = blockIdx.x * blockDim.x + threadIdx.x;   // over M_Q * (H/4)
    if (idx >= M_Q * (H_ / 4)) return;
    int m = idx >> 7;           // H/4 = 128
    int c = idx & 127;
    int b = m / T_, t = m % T_;
    int tok = targets[b * LSEQ + t];
    reinterpret_cast<float4*>(emb)[(size_t)m * 128 + c] =
        reinterpret_cast<const float4*>(embedding)[(size_t)tok * 128 + c];
}

// ---------------- generic SGEMM: C[M,N] = A[M,K] * B[N,K]^T (+bias +bias2 +resid) ----------------
// BM=128, BN=64, BK=16, 256 threads, 8x4 per-thread tile. K must be %16 == 0.
__global__ __launch_bounds__(256)
void sgemm_kernel(const float* __restrict__ A, const float* __restrict__ Bw,
                  const float* __restrict__ bias, const float* __restrict__ bias2,
                  const float* __restrict__ resid, float* __restrict__ C,
                  int M, int N, int K)
{
    __shared__ float As[16][128];
    __shared__ float Bs[16][64];

    const int tid = threadIdx.x;
    const int bm = blockIdx.y * 128;
    const int bn = blockIdx.x * 64;
    const int tx = tid & 15;      // n-dir
    const int ty = tid >> 4;      // m-dir

    float acc[8][4];
#pragma unroll
    for (int i = 0; i < 8; i++)
#pragma unroll
        for (int j = 0; j < 4; j++) acc[i][j] = 0.f;

    const float4 zero4 = make_float4(0.f, 0.f, 0.f, 0.f);
    const int nkt = K >> 4;

    for (int kt = 0; kt < nkt; kt++) {
        // load A tile (128 x 16): 2 float4 per thread, transposed into As[k][m]
#pragma unroll
        for (int i = 0; i < 2; i++) {
            int flat = tid * 2 + i;           // 0..511
            int m = flat >> 2;
            int kc = (flat & 3) << 2;
            int gm = bm + m;
            float4 v = (gm < M) ? *reinterpret_cast<const float4*>(&A[(size_t)gm * K + kt * 16 + kc])
                                : zero4;
            As[kc + 0][m] = v.x; As[kc + 1][m] = v.y;
            As[kc + 2][m] = v.z; As[kc + 3][m] = v.w;
        }
        // load B tile (64 x 16): 1 float4 per thread
        {
            int n = tid >> 2;
            int kc = (tid & 3) << 2;
            int gn = bn + n;
            float4 v = (gn < N) ? *reinterpret_cast<const float4*>(&Bw[(size_t)gn * K + kt * 16 + kc])
                                : zero4;
            Bs[kc + 0][n] = v.x; Bs[kc + 1][n] = v.y;
            Bs[kc + 2][n] = v.z; Bs[kc + 3][n] = v.w;
        }
        __syncthreads();

#pragma unroll
        for (int k = 0; k < 16; k++) {
            float a[8], b[4];
#pragma unroll
            for (int j = 0; j < 8; j++) a[j] = As[k][ty * 8 + j];
#pragma unroll
            for (int j = 0; j < 4; j++) b[j] = Bs[k][tx * 4 + j];
#pragma unroll
            for (int i = 0; i < 8; i++)
#pragma unroll
                for (int j = 0; j < 4; j++) acc[i][j] += a[i] * b[j];
        }
        __syncthreads();
    }

#pragma unroll
    for (int i = 0; i < 8; i++) {
        int gm = bm + ty * 8 + i;
        if (gm >= M) continue;
#pragma unroll
        for (int j = 0; j < 4; j++) {
            int gn = bn + tx * 4 + j;
            if (gn >= N) continue;
            float v = acc[i][j];
            if (bias)  v += bias[gn];
            if (bias2) v += bias2[gn];
            if (resid) v += resid[(size_t)gm * N + gn];
            C[(size_t)gm * N + gn] = v;
        }
    }
}

// ---------------- persistent LSTM ----------------
__device__ __forceinline__ float sigmoidf_(float x) { return 1.f / (1.f + expf(-x)); }

__device__ __forceinline__ void grid_barrier(unsigned nblk)
{
    __syncthreads();
    if (threadIdx.x == 0) {
        __threadfence();
        unsigned gen = g_bar_gen;
        if (atomicAdd(&g_bar_count, 1) == nblk - 1) {
            g_bar_count = 0;
            __threadfence();
            g_bar_gen = gen + 1;
        } else {
            while (g_bar_gen == gen) { __nanosleep(32); }
        }
    }
    __syncthreads();
}

// 128 blocks x 256 threads. Block bi owns j in [bi*4, bi*4+4) of the hidden dim,
// computing all 4 gates for all 32 batches: a 32 x 16 x 512 GEMM slice per step.
__global__ __launch_bounds__(256)
void lstm_kernel(const float* __restrict__ xg, const float* __restrict__ w_hh,
                 float* __restrict__ lstm_out)
{
    const int bi = blockIdx.x;
    const int tid = threadIdx.x;
    const int j0 = bi * 4;

    __shared__ float hs[32][65];     // padded: conflict-free hs[batch][k]
    __shared__ float ws[16][64];
    __shared__ float gates_s[32][16];

    const int tx = tid & 31;         // batch
    const int ty = tid >> 5;         // 0..7 -> rows 2ty, 2ty+1

    // zero init owned slice of c and h(parity 0)
    if (tid < 128) {
        int b = tid & 31, jj = tid >> 5;
        g_cbuf[b * H_ + j0 + jj] = 0.f;
        g_hbuf[b * H_ + j0 + jj] = 0.f;
    }
    grid_barrier(gridDim.x);

    const int r0 = 2 * ty, r1 = 2 * ty + 1;

    for (int t = 0; t < T_; t++) {
        const float* h_old = g_hbuf + (t & 1) * (B_ * H_);
        float* h_new = g_hbuf + ((t + 1) & 1) * (B_ * H_);

        float acc0 = 0.f, acc1 = 0.f;

        for (int kc = 0; kc < 8; kc++) {
            // stage h tile [32][64] (cross-SM coherent: bypass L1)
#pragma unroll
            for (int i = 0; i < 2; i++) {
                int flat4 = tid * 2 + i;           // 0..511
                int b = flat4 >> 4;
                int c4 = (flat4 & 15) << 2;
                float4 v = __ldcg(reinterpret_cast<const float4*>(&h_old[b * H_ + kc * 64 + c4]));
                hs[b][c4 + 0] = v.x; hs[b][c4 + 1] = v.y;
                hs[b][c4 + 2] = v.z; hs[b][c4 + 3] = v.w;
            }
            // stage w_hh tile [16 rows][64]
            {
                int r = tid >> 4;
                int c4 = (tid & 15) << 2;
                int wrow = (r >> 2) * H_ + j0 + (r & 3);
                float4 v = *reinterpret_cast<const float4*>(&w_hh[(size_t)wrow * H_ + kc * 64 + c4]);
                ws[r][c4 + 0] = v.x; ws[r][c4 + 1] = v.y;
                ws[r][c4 + 2] = v.z; ws[r][c4 + 3] = v.w;
            }
            __syncthreads();
#pragma unroll
            for (int kk = 0; kk < 64; kk++) {
                float a = hs[tx][kk];
                acc0 += a * ws[r0][kk];
                acc1 += a * ws[r1][kk];
            }
            __syncthreads();
        }

        gates_s[tx][r0] = acc0;
        gates_s[tx][r1] = acc1;
        __syncthreads();

        if (tid < 128) {
            int b = tid & 31, jj = tid >> 5;
            int j = j0 + jj;
            size_t mbase = (size_t)(b * T_ + t) * (4 * H_);
            float gi = xg[mbase + 0 * H_ + j] + gates_s[b][0  + jj];
            float gf = xg[mbase + 1 * H_ + j] + gates_s[b][4  + jj];
            float gg = xg[mbase + 2 * H_ + j] + gates_s[b][8  + jj];
            float go = xg[mbase + 3 * H_ + j] + gates_s[b][12 + jj];
            float ig = sigmoidf_(gi);
            float fg = sigmoidf_(gf);
            float g2 = tanhf(gg);
            float og = sigmoidf_(go);
            float c = fg * g_cbuf[b * H_ + j] + ig * g2;
            g_cbuf[b * H_ + j] = c;
            float h = og * tanhf(c);
            __stcg(&h_new[b * H_ + j], h);
            lstm_out[(size_t)(b * T_ + t) * H_ + j] = h;
        }
        __syncthreads();
        grid_barrier(gridDim.x);
    }
}

// ---------------- attention: one block per (b, head), one t-row per thread ----------------
__global__ __launch_bounds__(128)
void attn_kernel(const float* __restrict__ q, const float* __restrict__ kbuf,
                 const float* __restrict__ vbuf, float* __restrict__ ctx)
{
    const int bh = blockIdx.x;
    const int b = bh >> 3;
    const int h = bh & 7;
    const int tid = threadIdx.x;
    const bool active = tid < T_;

    __shared__ float4 ks[32][16];
    __shared__ float4 vs[32][16];

    float4 qv[16], av[16];
#pragma unroll
    for (int i = 0; i < 16; i++) av[i] = make_float4(0.f, 0.f, 0.f, 0.f);

    if (active) {
        size_t qrow = (size_t)(b * T_ + tid) * H_ + h * HD_;
#pragma unroll
        for (int i = 0; i < 16; i++)
            qv[i] = *reinterpret_cast<const float4*>(&q[qrow + i * 4]);
    } else {
#pragma unroll
        for (int i = 0; i < 16; i++) qv[i] = make_float4(0.f, 0.f, 0.f, 0.f);
    }

    float l = 0.f;
    for (int s0 = 0; s0 < S_; s0 += 32) {
#pragma unroll
        for (int i = 0; i < 4; i++) {
            int flat = tid + i * 128;          // 0..511
            int ss = flat >> 4;
            int d4 = flat & 15;
            size_t krow = (size_t)(b * S_ + s0 + ss) * H_ + h * HD_;
            ks[ss][d4] = *reinterpret_cast<const float4*>(&kbuf[krow + d4 * 4]);
            vs[ss][d4] = *reinterpret_cast<const float4*>(&vbuf[krow + d4 * 4]);
        }
        __syncthreads();
        if (active) {
            for (int ss = 0; ss < 32; ss++) {
                float s = 0.f;
#pragma unroll
                for (int i = 0; i < 16; i++) {
                    float4 kk = ks[ss][i];
                    s += qv[i].x * kk.x + qv[i].y * kk.y + qv[i].z * kk.z + qv[i].w * kk.w;
                }
                // scores are tiny (weights * 0.02): softmax without max-subtraction is exact here
                float p = __expf(s * 0.125f);
                l += p;
#pragma unroll
                for (int i = 0; i < 16; i++) {
                    float4 vv = vs[ss][i];
                    av[i].x += p * vv.x; av[i].y += p * vv.y;
                    av[i].z += p * vv.z; av[i].w += p * vv.w;
                }
            }
        }
        __syncthreads();
    }

    if (active) {
        float inv = 1.f / l;
        size_t crow = (size_t)(b * T_ + tid) * H_ + h * HD_;
#pragma unroll
        for (int i = 0; i < 16; i++) {
            float4 o = make_float4(av[i].x * inv, av[i].y * inv, av[i].z * inv, av[i].w * inv);
            *reinterpret_cast<float4*>(&ctx[crow + i * 4]) = o;
        }
    }
}

// ---------------- launch ----------------
extern "C" void kernel_launch(void* const* d_in, const int* in_sizes, int n_in,
                              void* d_out, int out_size)
{
    const int*   targets    = (const int*)  d_in[0];
    const float* enc        = (const float*)d_in[1];
    const float* embedding  = (const float*)d_in[2];
    const float* w_ih       = (const float*)d_in[3];
    const float* w_hh       = (const float*)d_in[4];
    const float* b_ih       = (const float*)d_in[5];
    const float* b_hh       = (const float*)d_in[6];
    const float* in_proj_w  = (const float*)d_in[7];
    const float* in_proj_b  = (const float*)d_in[8];
    const float* out_proj_w = (const float*)d_in[9];
    const float* out_proj_b = (const float*)d_in[10];
    const float* fc_w       = (const float*)d_in[11];
    const float* fc_b       = (const float*)d_in[12];
    float* out = (float*)d_out;

    float *emb, *xg, *lstm, *q, *k, *v, *ctx, *comb;
    cudaGetSymbolAddress((void**)&emb,  g_emb);
    cudaGetSymbolAddress((void**)&xg,   g_xg);
    cudaGetSymbolAddress((void**)&lstm, g_lstm);
    cudaGetSymbolAddress((void**)&q,    g_q);
    cudaGetSymbolAddress((void**)&k,    g_k);
    cudaGetSymbolAddress((void**)&v,    g_v);
    cudaGetSymbolAddress((void**)&ctx,  g_ctx);
    cudaGetSymbolAddress((void**)&comb, g_comb);

    // 1. gather embeddings
    gather_kernel<<<(M_Q * (H_ / 4) + 255) / 256, 256>>>(targets, embedding, emb);

    // 2. xg = emb @ w_ih^T + b_ih + b_hh   [4064, 2048]
    sgemm_kernel<<<dim3(4 * H_ / 64, (M_Q + 127) / 128), 256>>>(
        emb, w_ih, b_ih, b_hh, nullptr, xg, M_Q, 4 * H_, H_);

    // 3. k/v projections from encoder outputs  [8192, 512]
    sgemm_kernel<<<dim3(H_ / 64, M_KV / 128), 256>>>(
        enc, in_proj_w + (size_t)H_ * H_, in_proj_b + H_, nullptr, nullptr, k, M_KV, H_, H_);
    sgemm_kernel<<<dim3(H_ / 64, M_KV / 128), 256>>>(
        enc, in_proj_w + (size_t)2 * H_ * H_, in_proj_b + 2 * H_, nullptr, nullptr, v, M_KV, H_, H_);

    // 4. LSTM recurrence (persistent, grid-barrier per step)
    lstm_kernel<<<128, 256>>>(xg, w_hh, lstm);

    // 5. q projection  [4064, 512]
    sgemm_kernel<<<dim3(H_ / 64, (M_Q + 127) / 128), 256>>>(
        lstm, in_proj_w, in_proj_b, nullptr, nullptr, q, M_Q, H_, H_);

    // 6. attention -> ctx
    attn_kernel<<<B_ * NH_, 128>>>(q, k, v, ctx);

    // 7. combined = ctx @ out_proj^T + out_proj_b + lstm_out
    sgemm_kernel<<<dim3(H_ / 64, (M_Q + 127) / 128), 256>>>(
        ctx, out_proj_w, out_proj_b, nullptr, lstm, comb, M_Q, H_, H_);

    // 8. out = combined @ fc_w^T + fc_b   [4064, 8000]
    sgemm_kernel<<<dim3(V_ / 64, (M_Q + 127) / 128), 256>>>(
        comb, fc_w, fc_b, nullptr, nullptr, out, M_Q, V_, H_);
}

// round 15
// speedup vs baseline: 1.1638x; 1.1638x over previous
#include <cuda_runtime.h>
#include <cuda_bf16.h>
#include <math.h>

// ---------------- problem constants ----------------
#define B_   32
#define LSEQ 128
#define T_   127          // L-1
#define S_   256
#define H_   512
#define NH_  8
#define HD_  64
#define V_   8000
#define M_Q  (B_ * T_)    // 4064
#define M_KV (B_ * S_)    // 8192

// ---------------- packed f32x2 helpers (Blackwell FFMA2 path) ----------------
#define FMA_F32X2(d, a, b) \
    asm("fma.rn.f32x2 %0, %1, %2, %0;" : "+l"(d) : "l"(a), "l"(b))
#define PACK_DUP_F32X2(d, x) \
    asm("mov.b64 %0, {%1, %1};" : "=l"(d) : "f"(x))
#define UNPACK_F32X2_(lo, hi, in) \
    asm("mov.b64 {%0, %1}, %2;" : "=f"(lo), "=f"(hi) : "l"(in))

// ---------------- scratch (device globals; no allocation allowed) ----------------
__device__ float g_emb [M_Q * H_];
__device__ float g_xg  [M_Q * 4 * H_];
__device__ float g_lstm[M_Q * H_];
__device__ float g_hbuf[2 * B_ * H_];
__device__ float g_cbuf[B_ * H_];
__device__ float g_q   [M_Q * H_];
__device__ float g_k   [M_KV * H_];
__device__ float g_v   [M_KV * H_];
__device__ float g_ctx [M_Q * H_];
__device__ float g_comb[M_Q * H_];

// barrier state (returns to initial-compatible state every launch; gen monotone)
__device__ unsigned g_cnt[8 * 32];          // bucket counters, 128B apart
__device__ unsigned g_cnt_m = 0;
__device__ volatile unsigned g_bar_gen = 0;

// ---------------- gather ----------------
__global__ void gather_kernel(const int* __restrict__ targets,
                              const float* __restrict__ embedding,
                              float* __restrict__ emb)
{
    int idx = blockIdx.x * blockDim.x + threadIdx.x;
    if (idx >= M_Q * (H_ / 4)) return;
    int m = idx >> 7;
    int c = idx & 127;
    int b = m / T_, t = m % T_;
    int tok = targets[b * LSEQ + t];
    reinterpret_cast<float4*>(emb)[(size_t)m * 128 + c] =
        reinterpret_cast<const float4*>(embedding)[(size_t)tok * 128 + c];
}

// ---------------- SGEMM with FFMA2: C[M,N] = A[M,K]*B[N,K]^T (+bias+bias2+resid) ----------------
// BM=128, BN=64, BK=16, 256 threads, 8x4 per-thread tile (as 4 m-pairs x 4 n).
__global__ __launch_bounds__(256)
void sgemm_kernel(const float* __restrict__ A, const float* __restrict__ Bw,
                  const float* __restrict__ bias, const float* __restrict__ bias2,
                  const float* __restrict__ resid, float* __restrict__ C,
                  int M, int N, int K)
{
    __shared__ float As[16][128];
    __shared__ float Bs[16][64];

    const int tid = threadIdx.x;
    const int bm = blockIdx.y * 128;
    const int bn = blockIdx.x * 64;
    const int tx = tid & 15;      // n-dir
    const int ty = tid >> 4;      // m-dir

    unsigned long long acc2[4][4];
#pragma unroll
    for (int mi = 0; mi < 4; mi++)
#pragma unroll
        for (int j = 0; j < 4; j++) acc2[mi][j] = 0ULL;

    const float4 zero4 = make_float4(0.f, 0.f, 0.f, 0.f);
    const int nkt = K >> 4;

    for (int kt = 0; kt < nkt; kt++) {
        // A tile (128 x 16), transposed into As[k][m]
#pragma unroll
        for (int i = 0; i < 2; i++) {
            int flat = tid * 2 + i;
            int m = flat >> 2;
            int kc = (flat & 3) << 2;
            int gm = bm + m;
            float4 v = (gm < M) ? *reinterpret_cast<const float4*>(&A[(size_t)gm * K + kt * 16 + kc])
                                : zero4;
            As[kc + 0][m] = v.x; As[kc + 1][m] = v.y;
            As[kc + 2][m] = v.z; As[kc + 3][m] = v.w;
        }
        // B tile (64 x 16)
        {
            int n = tid >> 2;
            int kc = (tid & 3) << 2;
            int gn = bn + n;
            float4 v = (gn < N) ? *reinterpret_cast<const float4*>(&Bw[(size_t)gn * K + kt * 16 + kc])
                                : zero4;
            Bs[kc + 0][n] = v.x; Bs[kc + 1][n] = v.y;
            Bs[kc + 2][n] = v.z; Bs[kc + 3][n] = v.w;
        }
        __syncthreads();

#pragma unroll
        for (int k = 0; k < 16; k++) {
            unsigned long long a2[4], b2[4];
#pragma unroll
            for (int mi = 0; mi < 4; mi++)
                a2[mi] = *reinterpret_cast<const unsigned long long*>(&As[k][ty * 8 + 2 * mi]);
            float4 bv = *reinterpret_cast<const float4*>(&Bs[k][tx * 4]);
            PACK_DUP_F32X2(b2[0], bv.x);
            PACK_DUP_F32X2(b2[1], bv.y);
            PACK_DUP_F32X2(b2[2], bv.z);
            PACK_DUP_F32X2(b2[3], bv.w);
#pragma unroll
            for (int mi = 0; mi < 4; mi++)
#pragma unroll
                for (int j = 0; j < 4; j++)
                    FMA_F32X2(acc2[mi][j], a2[mi], b2[j]);
        }
        __syncthreads();
    }

#pragma unroll
    for (int mi = 0; mi < 4; mi++) {
#pragma unroll
        for (int j = 0; j < 4; j++) {
            float lo, hi;
            UNPACK_F32X2_(lo, hi, acc2[mi][j]);
            int gm0 = bm + ty * 8 + 2 * mi;
            int gn  = bn + tx * 4 + j;
            if (gn < N) {
                float badd = (bias ? bias[gn] : 0.f) + (bias2 ? bias2[gn] : 0.f);
                if (gm0 < M) {
                    float v = lo + badd;
                    if (resid) v += resid[(size_t)gm0 * N + gn];
                    C[(size_t)gm0 * N + gn] = v;
                }
                if (gm0 + 1 < M) {
                    float v = hi + badd;
                    if (resid) v += resid[(size_t)(gm0 + 1) * N + gn];
                    C[(size_t)(gm0 + 1) * N + gn] = v;
                }
            }
        }
    }
}

// ---------------- persistent LSTM ----------------
__device__ __forceinline__ float sigmoidf_(float x) { return 1.f / (1.f + expf(-x)); }

// two-level barrier: 8 buckets x 16 arrivals, then 8 -> master
__device__ __forceinline__ void grid_barrier(int bi)
{
    __syncthreads();
    if (threadIdx.x == 0) {
        __threadfence();
        unsigned gen = g_bar_gen;
        unsigned bucket = (unsigned)bi & 7u;
        if (atomicAdd(&g_cnt[bucket * 32], 1u) == 15u) {
            if (atomicAdd(&g_cnt_m, 1u) == 7u) {
#pragma unroll
                for (int i = 0; i < 8; i++) g_cnt[i * 32] = 0u;
                g_cnt_m = 0u;
                __threadfence();
                g_bar_gen = gen + 1u;
            }
        }
        while (g_bar_gen == gen) { __nanosleep(32); }
    }
    __syncthreads();
}

#define HS_STRIDE 33
// dyn smem: hsT [512][33] floats (67.6KB) + wp [8][512] float2 (32KB) + gsm [32][16] (2KB)
#define LSTM_SMEM_BYTES ((512 * HS_STRIDE + 8 * 512 * 2 + 32 * 16) * 4)

__global__ __launch_bounds__(256)
void lstm_kernel(const float* __restrict__ xg, const float* __restrict__ w_hh,
                 float* __restrict__ lstm_out)
{
    extern __shared__ float dsm[];
    float*  hsT = dsm;                               // [k][b] transposed, stride 33
    float2* wp  = reinterpret_cast<float2*>(dsm + 512 * HS_STRIDE);  // [8][512] row-pairs
    float*  gsm = dsm + 512 * HS_STRIDE + 8 * 512 * 2;               // [32][16]

    const int bi  = blockIdx.x;
    const int tid = threadIdx.x;
    const int j0  = bi * 4;
    const int tx  = tid & 31;     // batch
    const int ty  = tid >> 5;     // row-pair 0..7 -> rows 2ty, 2ty+1
    const int r0 = 2 * ty, r1 = 2 * ty + 1;

    // preload w_hh slice once: rows r=0..15 map to global row (r>>2)*H + j0 + (r&3),
    // stored interleaved as pairs wp[rp*512+k] = {w[2rp][k], w[2rp+1][k]}
    float* wpf = reinterpret_cast<float*>(wp);
#pragma unroll
    for (int it = 0; it < 8; it++) {
        int idx = tid + it * 256;          // float4 index over 16*128
        int r  = idx >> 7;                 // 0..15
        int c4 = (idx & 127) << 2;
        int wrow = (r >> 2) * H_ + j0 + (r & 3);
        float4 v = *reinterpret_cast<const float4*>(&w_hh[(size_t)wrow * H_ + c4]);
        int rp = r >> 1, lane = r & 1;
        wpf[(rp * 512 + c4 + 0) * 2 + lane] = v.x;
        wpf[(rp * 512 + c4 + 1) * 2 + lane] = v.y;
        wpf[(rp * 512 + c4 + 2) * 2 + lane] = v.z;
        wpf[(rp * 512 + c4 + 3) * 2 + lane] = v.w;
    }

    // zero init owned slice of c and h(parity 0)
    if (tid < 128) {
        int b = tid & 31, jj = tid >> 5;
        g_cbuf[b * H_ + j0 + jj] = 0.f;
        g_hbuf[b * H_ + j0 + jj] = 0.f;
    }
    grid_barrier(bi);

    for (int t = 0; t < T_; t++) {
        const float* h_old = g_hbuf + (t & 1) * (B_ * H_);
        float* h_new = g_hbuf + ((t + 1) & 1) * (B_ * H_);

        // stage FULL h [32][512] into transposed smem in one batched round
#pragma unroll
        for (int it = 0; it < 16; it++) {
            int idx = tid + it * 256;       // float4 index over 32*128
            int b  = idx >> 7;
            int c4 = (idx & 127) << 2;
            float4 v = __ldcg(reinterpret_cast<const float4*>(&h_old[b * H_ + c4]));
            hsT[(c4 + 0) * HS_STRIDE + b] = v.x;
            hsT[(c4 + 1) * HS_STRIDE + b] = v.y;
            hsT[(c4 + 2) * HS_STRIDE + b] = v.z;
            hsT[(c4 + 3) * HS_STRIDE + b] = v.w;
        }
        __syncthreads();

        float acc0 = 0.f, acc1 = 0.f;
        const float2* wrow = wp + ty * 512;
#pragma unroll 8
        for (int kk = 0; kk < 512; kk++) {
            float a = hsT[kk * HS_STRIDE + tx];
            float2 w2 = wrow[kk];            // broadcast LDS.64
            acc0 += a * w2.x;
            acc1 += a * w2.y;
        }
        gsm[tx * 16 + r0] = acc0;
        gsm[tx * 16 + r1] = acc1;
        __syncthreads();

        if (tid < 128) {
            int b = tid & 31, jj = tid >> 5;
            int j = j0 + jj;
            size_t mbase = (size_t)(b * T_ + t) * (4 * H_);
            float gi = xg[mbase + 0 * H_ + j] + gsm[b * 16 + 0  + jj];
            float gf = xg[mbase + 1 * H_ + j] + gsm[b * 16 + 4  + jj];
            float gg = xg[mbase + 2 * H_ + j] + gsm[b * 16 + 8  + jj];
            float go = xg[mbase + 3 * H_ + j] + gsm[b * 16 + 12 + jj];
            float ig = sigmoidf_(gi);
            float fg = sigmoidf_(gf);
            float g2 = tanhf(gg);
            float og = sigmoidf_(go);
            float c = fg * g_cbuf[b * H_ + j] + ig * g2;
            g_cbuf[b * H_ + j] = c;
            float h = og * tanhf(c);
            __stcg(&h_new[b * H_ + j], h);
            lstm_out[(size_t)(b * T_ + t) * H_ + j] = h;
        }
        grid_barrier(bi);
    }
}

// ---------------- attention ----------------
__global__ __launch_bounds__(128)
void attn_kernel(const float* __restrict__ q, const float* __restrict__ kbuf,
                 const float* __restrict__ vbuf, float* __restrict__ ctx)
{
    const int bh = blockIdx.x;
    const int b = bh >> 3;
    const int h = bh & 7;
    const int tid = threadIdx.x;
    const bool active = tid < T_;

    __shared__ float4 ks[32][16];
    __shared__ float4 vs[32][16];

    float4 qv[16], av[16];
#pragma unroll
    for (int i = 0; i < 16; i++) av[i] = make_float4(0.f, 0.f, 0.f, 0.f);

    if (active) {
        size_t qrow = (size_t)(b * T_ + tid) * H_ + h * HD_;
#pragma unroll
        for (int i = 0; i < 16; i++)
            qv[i] = *reinterpret_cast<const float4*>(&q[qrow + i * 4]);
    } else {
#pragma unroll
        for (int i = 0; i < 16; i++) qv[i] = make_float4(0.f, 0.f, 0.f, 0.f);
    }

    float l = 0.f;
    for (int s0 = 0; s0 < S_; s0 += 32) {
#pragma unroll
        for (int i = 0; i < 4; i++) {
            int flat = tid + i * 128;
            int ss = flat >> 4;
            int d4 = flat & 15;
            size_t krow = (size_t)(b * S_ + s0 + ss) * H_ + h * HD_;
            ks[ss][d4] = *reinterpret_cast<const float4*>(&kbuf[krow + d4 * 4]);
            vs[ss][d4] = *reinterpret_cast<const float4*>(&vbuf[krow + d4 * 4]);
        }
        __syncthreads();
        if (active) {
            for (int ss = 0; ss < 32; ss++) {
                float s = 0.f;
#pragma unroll
                for (int i = 0; i < 16; i++) {
                    float4 kk = ks[ss][i];
                    s += qv[i].x * kk.x + qv[i].y * kk.y + qv[i].z * kk.z + qv[i].w * kk.w;
                }
                float p = __expf(s * 0.125f);
                l += p;
#pragma unroll
                for (int i = 0; i < 16; i++) {
                    float4 vv = vs[ss][i];
                    av[i].x += p * vv.x; av[i].y += p * vv.y;
                    av[i].z += p * vv.z; av[i].w += p * vv.w;
                }
            }
        }
        __syncthreads();
    }

    if (active) {
        float inv = 1.f / l;
        size_t crow = (size_t)(b * T_ + tid) * H_ + h * HD_;
#pragma unroll
        for (int i = 0; i < 16; i++) {
            float4 o = make_float4(av[i].x * inv, av[i].y * inv, av[i].z * inv, av[i].w * inv);
            *reinterpret_cast<float4*>(&ctx[crow + i * 4]) = o;
        }
    }
}

// ---------------- launch ----------------
extern "C" void kernel_launch(void* const* d_in, const int* in_sizes, int n_in,
                              void* d_out, int out_size)
{
    const int*   targets    = (const int*)  d_in[0];
    const float* enc        = (const float*)d_in[1];
    const float* embedding  = (const float*)d_in[2];
    const float* w_ih       = (const float*)d_in[3];
    const float* w_hh       = (const float*)d_in[4];
    const float* b_ih       = (const float*)d_in[5];
    const float* b_hh       = (const float*)d_in[6];
    const float* in_proj_w  = (const float*)d_in[7];
    const float* in_proj_b  = (const float*)d_in[8];
    const float* out_proj_w = (const float*)d_in[9];
    const float* out_proj_b = (const float*)d_in[10];
    const float* fc_w       = (const float*)d_in[11];
    const float* fc_b       = (const float*)d_in[12];
    float* out = (float*)d_out;

    float *emb, *xg, *lstm, *q, *k, *v, *ctx, *comb;
    cudaGetSymbolAddress((void**)&emb,  g_emb);
    cudaGetSymbolAddress((void**)&xg,   g_xg);
    cudaGetSymbolAddress((void**)&lstm, g_lstm);
    cudaGetSymbolAddress((void**)&q,    g_q);
    cudaGetSymbolAddress((void**)&k,    g_k);
    cudaGetSymbolAddress((void**)&v,    g_v);
    cudaGetSymbolAddress((void**)&ctx,  g_ctx);
    cudaGetSymbolAddress((void**)&comb, g_comb);

    cudaFuncSetAttribute(lstm_kernel, cudaFuncAttributeMaxDynamicSharedMemorySize,
                         LSTM_SMEM_BYTES);

    // 1. gather embeddings
    gather_kernel<<<(M_Q * (H_ / 4) + 255) / 256, 256>>>(targets, embedding, emb);

    // 2. xg = emb @ w_ih^T + b_ih + b_hh
    sgemm_kernel<<<dim3(4 * H_ / 64, (M_Q + 127) / 128), 256>>>(
        emb, w_ih, b_ih, b_hh, nullptr, xg, M_Q, 4 * H_, H_);

    // 3. k/v projections
    sgemm_kernel<<<dim3(H_ / 64, M_KV / 128), 256>>>(
        enc, in_proj_w + (size_t)H_ * H_, in_proj_b + H_, nullptr, nullptr, k, M_KV, H_, H_);
    sgemm_kernel<<<dim3(H_ / 64, M_KV / 128), 256>>>(
        enc, in_proj_w + (size_t)2 * H_ * H_, in_proj_b + 2 * H_, nullptr, nullptr, v, M_KV, H_, H_);

    // 4. LSTM recurrence (persistent)
    lstm_kernel<<<128, 256, LSTM_SMEM_BYTES>>>(xg, w_hh, lstm);

    // 5. q projection
    sgemm_kernel<<<dim3(H_ / 64, (M_Q + 127) / 128), 256>>>(
        lstm, in_proj_w, in_proj_b, nullptr, nullptr, q, M_Q, H_, H_);

    // 6. attention -> ctx
    attn_kernel<<<B_ * NH_, 128>>>(q, k, v, ctx);

    // 7. combined = ctx @ out_proj^T + out_proj_b + lstm_out
    sgemm_kernel<<<dim3(H_ / 64, (M_Q + 127) / 128), 256>>>(
        ctx, out_proj_w, out_proj_b, nullptr, lstm, comb, M_Q, H_, H_);

    // 8. out = combined @ fc_w^T + fc_b
    sgemm_kernel<<<dim3(V_ / 64, (M_Q + 127) / 128), 256>>>(
        comb, fc_w, fc_b, nullptr, nullptr, out, M_Q, V_, H_);
}